// round 9
// baseline (speedup 1.0000x reference)
#include <cuda_runtime.h>
#include <stdint.h>
#include <math.h>

// out = gelu_tanh(x) * gate
// gate = 1 + exp(log_alpha) * tanh(exp(log_sigma) * surp)
// surp = N/(2(N-1)) exactly (double-argsort ranks are always a permutation).
//
// gelu_tanh(x) = x / (1 + exp2(k * x * (1 + c1*x^2))), k = -2*sqrt(2/pi)*log2(e)
// ILP=8 float4 per thread, batched loads (4KB in flight per warp), plus
// ld.global.cs / st.global.cs streaming hints: zero-reuse data, evict-first
// keeps the 268MB stream from thrashing the 126MB L2 (write-allocate pressure
// was capping DRAM at 74.7%).

__device__ __forceinline__ float ex2_approx(float x) {
    float r; asm("ex2.approx.ftz.f32 %0, %1;" : "=f"(r) : "f"(x)); return r;
}
__device__ __forceinline__ float rcp_approx(float x) {
    float r; asm("rcp.approx.ftz.f32 %0, %1;" : "=f"(r) : "f"(x)); return r;
}

__device__ __forceinline__ float4 ldcs4(const float4* p) {
    float4 v;
    asm volatile("ld.global.cs.v4.f32 {%0,%1,%2,%3}, [%4];"
                 : "=f"(v.x), "=f"(v.y), "=f"(v.z), "=f"(v.w) : "l"(p));
    return v;
}
__device__ __forceinline__ void stcs4(float4* p, float4 v) {
    asm volatile("st.global.cs.v4.f32 [%0], {%1,%2,%3,%4};"
                 :: "l"(p), "f"(v.x), "f"(v.y), "f"(v.z), "f"(v.w));
}

__device__ __forceinline__ float gelu_fast(float x, float gate) {
    const float kNeg2C0Log2e = -2.0f * 0.7978845608028654f * 1.4426950408889634f;
    const float c1 = 0.044715f;
    float x2 = x * x;
    float xk = x * kNeg2C0Log2e;
    float u  = fmaf(c1 * x2, xk, xk);        // k*x*(1 + c1*x^2)
    float e  = ex2_approx(u);
    return (x * gate) * rcp_approx(e + 1.0f);
}

#define ILP 8

__global__ void __launch_bounds__(256)
gelu_gate_kernel(const float4* __restrict__ x,
                 const float* __restrict__ log_alpha,
                 const float* __restrict__ log_sigma,
                 float4* __restrict__ out,
                 int n4, float surp) {
    int tid    = blockIdx.x * blockDim.x + threadIdx.x;
    int stride = gridDim.x * blockDim.x;

    float alpha = __expf(log_alpha[0]);
    float sigma = __expf(log_sigma[0]);
    float gate  = fmaf(alpha, tanhf(sigma * surp), 1.0f);

    // Batch all loads first: MLP = ILP outstanding LDG.128 per thread.
    float4 v[ILP];
    int   idx[ILP];
    bool  ok[ILP];
    #pragma unroll
    for (int k = 0; k < ILP; k++) {
        idx[k] = tid + k * stride;
        ok[k]  = idx[k] < n4;
        if (ok[k]) v[k] = ldcs4(x + idx[k]);
    }

    #pragma unroll
    for (int k = 0; k < ILP; k++) {
        if (ok[k]) {
            float4 r;
            r.x = gelu_fast(v[k].x, gate);
            r.y = gelu_fast(v[k].y, gate);
            r.z = gelu_fast(v[k].z, gate);
            r.w = gelu_fast(v[k].w, gate);
            stcs4(out + idx[k], r);
        }
    }
}

extern "C" void kernel_launch(void* const* d_in, const int* in_sizes, int n_in,
                              void* d_out, int out_size) {
    const float* x         = (const float*)d_in[0];
    const float* log_alpha = (const float*)d_in[1];
    const float* log_sigma = (const float*)d_in[2];
    float* out             = (float*)d_out;

    long long n = in_sizes[0];          // B*T*D = 4*2048*4096
    const long long D = 4096;
    long long N = n / D;                // token count B*T = 8192
    float surp = (float)((double)N / (2.0 * (double)(N - 1)));

    int n4 = (int)(n / 4);
    int threads = 256;
    int blocks = (n4 + threads * ILP - 1) / (threads * ILP);
    gelu_gate_kernel<<<blocks, threads>>>(
        (const float4*)x, log_alpha, log_sigma, (float4*)out, n4, surp);
}

// round 15
// speedup vs baseline: 1.0210x; 1.0210x over previous
#include <cuda_runtime.h>
#include <stdint.h>
#include <math.h>

// out = gelu_tanh(x) * gate
// gate = 1 + exp(log_alpha) * tanh(exp(log_sigma) * surp)
// surp = N/(2(N-1)) exactly (double-argsort ranks are always a permutation).
//
// gelu_tanh(x) = x / (1 + exp2(k * x * (1 + c1*x^2))), k = -2*sqrt(2/pi)*log2(e)
//
// R5 post-mortem: ILP=8 cost occupancy (regs 48, occ 52%) and LOST bandwidth.
// Revert to ILP=4 (regs ~32, occ ~78%, the best measured point: 36.0us/74.7%),
// drop all bounds predicates via an exact-cover launch (n4 divisible by
// threads*ILP), keep streaming .cs hints.

__device__ __forceinline__ float ex2_approx(float x) {
    float r; asm("ex2.approx.ftz.f32 %0, %1;" : "=f"(r) : "f"(x)); return r;
}
__device__ __forceinline__ float rcp_approx(float x) {
    float r; asm("rcp.approx.ftz.f32 %0, %1;" : "=f"(r) : "f"(x)); return r;
}

__device__ __forceinline__ float4 ldcs4(const float4* p) {
    float4 v;
    asm volatile("ld.global.cs.v4.f32 {%0,%1,%2,%3}, [%4];"
                 : "=f"(v.x), "=f"(v.y), "=f"(v.z), "=f"(v.w) : "l"(p));
    return v;
}
__device__ __forceinline__ void stcs4(float4* p, float4 v) {
    asm volatile("st.global.cs.v4.f32 [%0], {%1,%2,%3,%4};"
                 :: "l"(p), "f"(v.x), "f"(v.y), "f"(v.z), "f"(v.w));
}

__device__ __forceinline__ float gelu_fast(float x, float gate) {
    const float kNeg2C0Log2e = -2.0f * 0.7978845608028654f * 1.4426950408889634f;
    const float c1 = 0.044715f;
    float x2 = x * x;
    float xk = x * kNeg2C0Log2e;
    float u  = fmaf(c1 * x2, xk, xk);        // k*x*(1 + c1*x^2)
    float e  = ex2_approx(u);
    return (x * gate) * rcp_approx(e + 1.0f);
}

#define ILP 4
#define THREADS 256

__device__ __forceinline__ float compute_gate(const float* la, const float* ls, float surp) {
    float alpha = __expf(la[0]);
    float sigma = __expf(ls[0]);
    return fmaf(alpha, tanhf(sigma * surp), 1.0f);
}

// Exact-cover kernel: no bounds checks, unconditional batched loads.
// Each CTA handles ILP contiguous chunks of THREADS float4s (block-linear).
__global__ void __launch_bounds__(THREADS)
gelu_gate_exact(const float4* __restrict__ x,
                const float* __restrict__ log_alpha,
                const float* __restrict__ log_sigma,
                float4* __restrict__ out,
                float surp) {
    int base = blockIdx.x * (THREADS * ILP) + threadIdx.x;

    float gate = compute_gate(log_alpha, log_sigma, surp);

    float4 v[ILP];
    #pragma unroll
    for (int k = 0; k < ILP; k++)
        v[k] = ldcs4(x + base + k * THREADS);

    #pragma unroll
    for (int k = 0; k < ILP; k++) {
        float4 r;
        r.x = gelu_fast(v[k].x, gate);
        r.y = gelu_fast(v[k].y, gate);
        r.z = gelu_fast(v[k].z, gate);
        r.w = gelu_fast(v[k].w, gate);
        stcs4(out + base + k * THREADS, r);
    }
}

// Guarded fallback for non-divisible sizes.
__global__ void __launch_bounds__(THREADS)
gelu_gate_guard(const float4* __restrict__ x,
                const float* __restrict__ log_alpha,
                const float* __restrict__ log_sigma,
                float4* __restrict__ out,
                int n4, float surp) {
    int base = blockIdx.x * (THREADS * ILP) + threadIdx.x;
    float gate = compute_gate(log_alpha, log_sigma, surp);

    float4 v[ILP];
    bool ok[ILP];
    #pragma unroll
    for (int k = 0; k < ILP; k++) {
        int i = base + k * THREADS;
        ok[k] = i < n4;
        if (ok[k]) v[k] = ldcs4(x + i);
    }
    #pragma unroll
    for (int k = 0; k < ILP; k++) {
        if (ok[k]) {
            float4 r;
            r.x = gelu_fast(v[k].x, gate);
            r.y = gelu_fast(v[k].y, gate);
            r.z = gelu_fast(v[k].z, gate);
            r.w = gelu_fast(v[k].w, gate);
            stcs4(out + base + k * THREADS, r);
        }
    }
}

extern "C" void kernel_launch(void* const* d_in, const int* in_sizes, int n_in,
                              void* d_out, int out_size) {
    const float* x         = (const float*)d_in[0];
    const float* log_alpha = (const float*)d_in[1];
    const float* log_sigma = (const float*)d_in[2];
    float* out             = (float*)d_out;

    long long n = in_sizes[0];          // B*T*D = 4*2048*4096
    const long long D = 4096;
    long long N = n / D;                // token count B*T = 8192
    float surp = (float)((double)N / (2.0 * (double)(N - 1)));

    int n4 = (int)(n / 4);
    const int per_block = THREADS * ILP;
    if (n4 % per_block == 0) {
        gelu_gate_exact<<<n4 / per_block, THREADS>>>(
            (const float4*)x, log_alpha, log_sigma, (float4*)out, surp);
    } else {
        int blocks = (n4 + per_block - 1) / per_block;
        gelu_gate_guard<<<blocks, THREADS>>>(
            (const float4*)x, log_alpha, log_sigma, (float4*)out, n4, surp);
    }
}